// round 12
// baseline (speedup 1.0000x reference)
#include <cuda_runtime.h>

#define BATCH 2048
#define T 128
#define NS 16
#define MS 8
#define CS 4
#define DT 0.01f
#define SB 16   // batches per block in staged states

// Batch-independent tables (L2-resident) + per-batch affine terms.
__device__ float g_K2[T * NS * MS];             // K[t][i][q]
__device__ float g_Pf[(T - 1) * NS * NS];       // P_f[t]
__device__ float g_G[(T - 1) * NS * NS];        // G[t][i][j]
__device__ float g_sp[(size_t)BATCH * T * NS];  // predicted states (t>=1)
__device__ float g_c[(size_t)BATCH * (T - 1) * NS];  // c[b][t] = sf[t]-G sp[t+1]

__device__ __forceinline__ float4 ld4(const float* p) { return *reinterpret_cast<const float4*>(p); }
__device__ __forceinline__ void st4(float* p, float4 v) { *reinterpret_cast<float4*>(p) = v; }
__device__ __forceinline__ float rcpa(float x) { float y; asm("rcp.approx.f32 %0, %1;" : "=f"(y) : "f"(x)); return y; }
__device__ __forceinline__ float shfl(float v, int s) { return __shfl_sync(0xffffffffu, v, s); }
__device__ __forceinline__ float shflx(float v, int m) { return __shfl_xor_sync(0xffffffffu, v, m); }
__device__ __forceinline__ float shfl16(float v, int s) { return __shfl_sync(0xffffffffu, v, s, 16); }

// ============================================================================
// Kernel A: batch-independent Riccati recursion (ONE warp, serial over T).
// 16-deep chains split into 2 accumulators to shorten the critical path.
// ============================================================================
__global__ __launch_bounds__(32) void kf_gains(
    const float* __restrict__ P0, const float* __restrict__ A,
    const float* __restrict__ H, const float* __restrict__ Q,
    const float* __restrict__ R)
{
    __shared__ float Fb[16 * 20], Ftb[16 * 20], Qb[16 * 20];
    __shared__ float Hb[8 * 20], Ht[16 * 8], Rb[64];
    __shared__ float P[16 * 20], PHt[16 * 8], X2[8 * 20];

    const int lane = threadIdx.x;
    for (int idx = lane; idx < 256; idx += 32) {
        int i = idx >> 4, k = idx & 15;
        float a = A[idx];
        float f = (i == k ? 1.0f : 0.0f) + DT * a;
        Fb[i * 20 + k] = f; Ftb[k * 20 + i] = f;
        Qb[i * 20 + k] = Q[idx];
        P[i * 20 + k] = P0[idx];
    }
    for (int idx = lane; idx < 128; idx += 32) {
        int q = idx >> 4, k = idx & 15;
        float h = H[idx];
        Hb[q * 20 + k] = h; Ht[k * 8 + q] = h;
    }
    for (int idx = lane; idx < 64; idx += 32) Rb[idx] = R[idx];
    __syncwarp();

    const int row = lane >> 1, h = lane & 1, j0 = h * 8;
    const int rr = row & 7;

    float frow[16];
    #pragma unroll
    for (int k = 0; k < 16; ++k) frow[k] = Fb[row * 20 + k];

    float a[8], w[8];

    for (int t = 0; t < T; ++t) {
        // W = F * P  (2-acc split)
        {
            float wA[8], wB[8];
            #pragma unroll
            for (int j = 0; j < 8; ++j) { wA[j] = 0.f; wB[j] = 0.f; }
            #pragma unroll
            for (int k = 0; k < 8; ++k) {
                float fv = frow[k];
                float4 p0 = ld4(&P[k * 20 + j0]);
                float4 p1 = ld4(&P[k * 20 + j0 + 4]);
                wA[0] = fmaf(fv, p0.x, wA[0]); wA[1] = fmaf(fv, p0.y, wA[1]);
                wA[2] = fmaf(fv, p0.z, wA[2]); wA[3] = fmaf(fv, p0.w, wA[3]);
                wA[4] = fmaf(fv, p1.x, wA[4]); wA[5] = fmaf(fv, p1.y, wA[5]);
                wA[6] = fmaf(fv, p1.z, wA[6]); wA[7] = fmaf(fv, p1.w, wA[7]);
            }
            #pragma unroll
            for (int k = 8; k < 16; ++k) {
                float fv = frow[k];
                float4 p0 = ld4(&P[k * 20 + j0]);
                float4 p1 = ld4(&P[k * 20 + j0 + 4]);
                wB[0] = fmaf(fv, p0.x, wB[0]); wB[1] = fmaf(fv, p0.y, wB[1]);
                wB[2] = fmaf(fv, p0.z, wB[2]); wB[3] = fmaf(fv, p0.w, wB[3]);
                wB[4] = fmaf(fv, p1.x, wB[4]); wB[5] = fmaf(fv, p1.y, wB[5]);
                wB[6] = fmaf(fv, p1.z, wB[6]); wB[7] = fmaf(fv, p1.w, wB[7]);
            }
            #pragma unroll
            for (int j = 0; j < 8; ++j) w[j] = wA[j] + wB[j];
        }

        // PP = W * F^T + Q  (2-acc split; kept in regs a[])
        {
            float wk[16];
            #pragma unroll
            for (int j = 0; j < 8; ++j) {
                wk[j0 + j] = w[j];
                wk[(j0 ^ 8) + j] = shflx(w[j], 1);
            }
            float aA[8], aB[8];
            float4 q0 = ld4(&Qb[row * 20 + j0]);
            float4 q1 = ld4(&Qb[row * 20 + j0 + 4]);
            aA[0] = q0.x; aA[1] = q0.y; aA[2] = q0.z; aA[3] = q0.w;
            aA[4] = q1.x; aA[5] = q1.y; aA[6] = q1.z; aA[7] = q1.w;
            #pragma unroll
            for (int j = 0; j < 8; ++j) aB[j] = 0.f;
            #pragma unroll
            for (int k = 0; k < 8; ++k) {
                float wv = wk[k];
                float4 f0 = ld4(&Ftb[k * 20 + j0]);
                float4 f1 = ld4(&Ftb[k * 20 + j0 + 4]);
                aA[0] = fmaf(wv, f0.x, aA[0]); aA[1] = fmaf(wv, f0.y, aA[1]);
                aA[2] = fmaf(wv, f0.z, aA[2]); aA[3] = fmaf(wv, f0.w, aA[3]);
                aA[4] = fmaf(wv, f1.x, aA[4]); aA[5] = fmaf(wv, f1.y, aA[5]);
                aA[6] = fmaf(wv, f1.z, aA[6]); aA[7] = fmaf(wv, f1.w, aA[7]);
            }
            #pragma unroll
            for (int k = 8; k < 16; ++k) {
                float wv = wk[k];
                float4 f0 = ld4(&Ftb[k * 20 + j0]);
                float4 f1 = ld4(&Ftb[k * 20 + j0 + 4]);
                aB[0] = fmaf(wv, f0.x, aB[0]); aB[1] = fmaf(wv, f0.y, aB[1]);
                aB[2] = fmaf(wv, f0.z, aB[2]); aB[3] = fmaf(wv, f0.w, aB[3]);
                aB[4] = fmaf(wv, f1.x, aB[4]); aB[5] = fmaf(wv, f1.y, aB[5]);
                aB[6] = fmaf(wv, f1.z, aB[6]); aB[7] = fmaf(wv, f1.w, aB[7]);
            }
            #pragma unroll
            for (int j = 0; j < 8; ++j) a[j] = aA[j] + aB[j];
        }

        // PHt[i][q] = sum_k PP[i][k] * H[q][k]  (2-acc)
        {
            float pk[16];
            #pragma unroll
            for (int j = 0; j < 8; ++j) {
                pk[j0 + j] = a[j];
                pk[(j0 ^ 8) + j] = shflx(a[j], 1);
            }
            const int qh = h * 4;
            float4 accA = make_float4(0.f, 0.f, 0.f, 0.f);
            float4 accB = make_float4(0.f, 0.f, 0.f, 0.f);
            #pragma unroll
            for (int k = 0; k < 8; ++k) {
                float p = pk[k];
                float4 hv = ld4(&Ht[k * 8 + qh]);
                accA.x = fmaf(p, hv.x, accA.x); accA.y = fmaf(p, hv.y, accA.y);
                accA.z = fmaf(p, hv.z, accA.z); accA.w = fmaf(p, hv.w, accA.w);
            }
            #pragma unroll
            for (int k = 8; k < 16; ++k) {
                float p = pk[k];
                float4 hv = ld4(&Ht[k * 8 + qh]);
                accB.x = fmaf(p, hv.x, accB.x); accB.y = fmaf(p, hv.y, accB.y);
                accB.z = fmaf(p, hv.z, accB.z); accB.w = fmaf(p, hv.w, accB.w);
            }
            st4(&PHt[row * 8 + qh],
                make_float4(accA.x + accB.x, accA.y + accB.y,
                            accA.z + accB.z, accA.w + accB.w));
        }
        __syncwarp();

        // S rows + RHS into registers  (2-acc for S)
        float s4[4], rhs[8];
        {
            const int ch = h * 4;
            float sA0 = Rb[rr * 8 + ch],     sA1 = Rb[rr * 8 + ch + 1];
            float sA2 = Rb[rr * 8 + ch + 2], sA3 = Rb[rr * 8 + ch + 3];
            float sB0 = 0.f, sB1 = 0.f, sB2 = 0.f, sB3 = 0.f;
            #pragma unroll
            for (int k = 0; k < 8; ++k) {
                float hv = Hb[rr * 20 + k];
                float4 ph = ld4(&PHt[k * 8 + ch]);
                sA0 = fmaf(hv, ph.x, sA0); sA1 = fmaf(hv, ph.y, sA1);
                sA2 = fmaf(hv, ph.z, sA2); sA3 = fmaf(hv, ph.w, sA3);
            }
            #pragma unroll
            for (int k = 8; k < 16; ++k) {
                float hv = Hb[rr * 20 + k];
                float4 ph = ld4(&PHt[k * 8 + ch]);
                sB0 = fmaf(hv, ph.x, sB0); sB1 = fmaf(hv, ph.y, sB1);
                sB2 = fmaf(hv, ph.z, sB2); sB3 = fmaf(hv, ph.w, sB3);
            }
            s4[0] = sA0 + sB0; s4[1] = sA1 + sB1;
            s4[2] = sA2 + sB2; s4[3] = sA3 + sB3;
            #pragma unroll
            for (int j = 0; j < 8; ++j)
                rhs[j] = PHt[(h * 8 + j) * 8 + rr];
        }

        // GJ solve S * X2 = PHt^T (8x8); K = X2^T
        {
            #pragma unroll
            for (int p = 0; p < 8; ++p) {
                const int hp = (p >= 4) ? 1 : 0;
                float cand = s4[p & 3];
                float f_num = shfl(cand, (rr << 1) | hp);
                float diag  = shfl(cand, (p << 1) | hp);
                const int src = (p << 1) | h;
                float ps0 = shfl(s4[0], src), ps1 = shfl(s4[1], src);
                float ps2 = shfl(s4[2], src), ps3 = shfl(s4[3], src);
                float pr[8];
                #pragma unroll
                for (int j = 0; j < 8; ++j) pr[j] = shfl(rhs[j], src);
                float f = (rr == p) ? 0.0f : f_num * rcpa(diag);
                s4[0] = fmaf(-f, ps0, s4[0]); s4[1] = fmaf(-f, ps1, s4[1]);
                s4[2] = fmaf(-f, ps2, s4[2]); s4[3] = fmaf(-f, ps3, s4[3]);
                #pragma unroll
                for (int j = 0; j < 8; ++j) rhs[j] = fmaf(-f, pr[j], rhs[j]);
            }
            float s01 = (rr & 1) ? s4[1] : s4[0];
            float s23 = (rr & 1) ? s4[3] : s4[2];
            float cand_r = (rr & 2) ? s23 : s01;
            float diag_r = shfl(cand_r, (rr << 1) | ((rr >= 4) ? 1 : 0));
            float invd = rcpa(diag_r);
            if (lane < 16) {
                st4(&X2[rr * 20 + h * 8],
                    make_float4(rhs[0] * invd, rhs[1] * invd, rhs[2] * invd, rhs[3] * invd));
                st4(&X2[rr * 20 + h * 8 + 4],
                    make_float4(rhs[4] * invd, rhs[5] * invd, rhs[6] * invd, rhs[7] * invd));
                #pragma unroll
                for (int j = 0; j < 8; ++j)
                    g_K2[t * 128 + (h * 8 + j) * 8 + rr] = rhs[j] * invd;
            }
        }
        __syncwarp();

        // P_f = PP - K*(H*PP);  (H*PP)[q][j] = PHt[j][q]  (2-acc)
        {
            float kq[8];
            #pragma unroll
            for (int q = 0; q < 8; ++q) kq[q] = X2[q * 20 + row];
            float n[8];
            #pragma unroll
            for (int j = 0; j < 8; ++j) {
                float4 p0 = ld4(&PHt[(j0 + j) * 8]);
                float4 p1 = ld4(&PHt[(j0 + j) * 8 + 4]);
                float vA = a[j], vB = 0.f;
                vA = fmaf(-kq[0], p0.x, vA); vA = fmaf(-kq[1], p0.y, vA);
                vA = fmaf(-kq[2], p0.z, vA); vA = fmaf(-kq[3], p0.w, vA);
                vB = fmaf(-kq[4], p1.x, vB); vB = fmaf(-kq[5], p1.y, vB);
                vB = fmaf(-kq[6], p1.z, vB); vB = fmaf(-kq[7], p1.w, vB);
                n[j] = vA + vB;
            }
            float4 v0 = make_float4(n[0], n[1], n[2], n[3]);
            float4 v1 = make_float4(n[4], n[5], n[6], n[7]);
            st4(&P[row * 20 + j0], v0);
            st4(&P[row * 20 + j0 + 4], v1);
            if (t < T - 1) {
                st4(&g_Pf[t * 256 + row * 16 + j0], v0);
                st4(&g_Pf[t * 256 + row * 16 + j0 + 4], v1);
            }
        }
        __syncwarp();
    }
}

// ============================================================================
// Kernel B: smoother gains, T-1 parallel warps. g_G[t][i][j] row-major.
// ============================================================================
__global__ __launch_bounds__(32) void kf_smoother_gains(
    const float* __restrict__ A, const float* __restrict__ Q)
{
    __shared__ float Fb[16 * 20], Ftb[16 * 20], Qb[16 * 20], Pf[16 * 20];
    const int t = blockIdx.x;
    const int lane = threadIdx.x;

    for (int idx = lane; idx < 256; idx += 32) {
        int i = idx >> 4, k = idx & 15;
        float av = A[idx];
        float f = (i == k ? 1.0f : 0.0f) + DT * av;
        Fb[i * 20 + k] = f; Ftb[k * 20 + i] = f;
        Qb[i * 20 + k] = Q[idx];
        Pf[i * 20 + k] = g_Pf[t * 256 + idx];
    }
    __syncwarp();

    const int row = lane >> 1, h = lane & 1, j0 = h * 8;
    float frow[16];
    #pragma unroll
    for (int k = 0; k < 16; ++k) frow[k] = Fb[row * 20 + k];

    float a[8], w[8];
    #pragma unroll
    for (int j = 0; j < 8; ++j) w[j] = 0.0f;
    #pragma unroll
    for (int k = 0; k < 16; ++k) {
        float fv = frow[k];
        float4 p0 = ld4(&Pf[k * 20 + j0]);
        float4 p1 = ld4(&Pf[k * 20 + j0 + 4]);
        w[0] = fmaf(fv, p0.x, w[0]); w[1] = fmaf(fv, p0.y, w[1]);
        w[2] = fmaf(fv, p0.z, w[2]); w[3] = fmaf(fv, p0.w, w[3]);
        w[4] = fmaf(fv, p1.x, w[4]); w[5] = fmaf(fv, p1.y, w[5]);
        w[6] = fmaf(fv, p1.z, w[6]); w[7] = fmaf(fv, p1.w, w[7]);
    }
    {
        float wk[16];
        #pragma unroll
        for (int j = 0; j < 8; ++j) {
            wk[j0 + j] = w[j];
            wk[(j0 ^ 8) + j] = shflx(w[j], 1);
        }
        float4 q0 = ld4(&Qb[row * 20 + j0]);
        float4 q1 = ld4(&Qb[row * 20 + j0 + 4]);
        a[0] = q0.x; a[1] = q0.y; a[2] = q0.z; a[3] = q0.w;
        a[4] = q1.x; a[5] = q1.y; a[6] = q1.z; a[7] = q1.w;
        #pragma unroll
        for (int k = 0; k < 16; ++k) {
            float wv = wk[k];
            float4 f0 = ld4(&Ftb[k * 20 + j0]);
            float4 f1 = ld4(&Ftb[k * 20 + j0 + 4]);
            a[0] = fmaf(wv, f0.x, a[0]); a[1] = fmaf(wv, f0.y, a[1]);
            a[2] = fmaf(wv, f0.z, a[2]); a[3] = fmaf(wv, f0.w, a[3]);
            a[4] = fmaf(wv, f1.x, a[4]); a[5] = fmaf(wv, f1.y, a[5]);
            a[6] = fmaf(wv, f1.z, a[6]); a[7] = fmaf(wv, f1.w, a[7]);
        }
    }
    #pragma unroll
    for (int p = 0; p < 16; ++p) {
        const int hp = (p >= 8) ? 1 : 0;
        float cand = a[p & 7];
        float f_num = shfl(cand, (row << 1) | hp);
        float diag  = shfl(cand, (p << 1) | hp);
        const int src = (p << 1) | h;
        float pa[8], pw[8];
        #pragma unroll
        for (int j = 0; j < 8; ++j) { pa[j] = shfl(a[j], src); pw[j] = shfl(w[j], src); }
        float f = (row == p) ? 0.0f : f_num * rcpa(diag);
        #pragma unroll
        for (int j = 0; j < 8; ++j) {
            a[j] = fmaf(-f, pa[j], a[j]);
            w[j] = fmaf(-f, pw[j], w[j]);
        }
    }
    const int ri = row & 7;
    float s01 = (ri & 1) ? a[1] : a[0];
    float s23 = (ri & 1) ? a[3] : a[2];
    float s45 = (ri & 1) ? a[5] : a[4];
    float s67 = (ri & 1) ? a[7] : a[6];
    float t0 = (ri & 2) ? s23 : s01;
    float t1 = (ri & 2) ? s67 : s45;
    float cand_r = (ri & 4) ? t1 : t0;
    float diag_r = shfl(cand_r, (row << 1) | ((row >= 8) ? 1 : 0));
    float invd = rcpa(diag_r);
    // lane holds X[row][j0+j] with X = G^T; store G rows: g_G[t][i=j0+j][row]
    #pragma unroll
    for (int j = 0; j < 8; ++j)
        g_G[t * 256 + (j0 + j) * 16 + row] = w[j] * invd;
}

// ============================================================================
// Kernel C: forward state filter, smem-staged (R6-best): K + u + y in smem,
// zero global loads in the scan loop.
// ============================================================================
__global__ __launch_bounds__(256) void kf_states(
    const float* __restrict__ state0, const float* __restrict__ controls,
    const float* __restrict__ obs, const float* __restrict__ A,
    const float* __restrict__ Bc, const float* __restrict__ H,
    float* __restrict__ out)
{
    extern __shared__ float sm[];
    float* Ks = sm;                        // T*128 = 16384 floats (transposed K)
    float* us = Ks + T * 128;              // SB*T*4 = 8192
    float* ys = us + SB * T * 4;           // SB*T*8 = 16384

    const int tid = threadIdx.x;
    const int b0 = blockIdx.x * SB;

    for (int idx = tid; idx < 4096; idx += 256)
        st4(&Ks[idx * 4], ld4(&g_K2[idx * 4]));
    {
        const float* src = controls + (size_t)b0 * T * 4;
        for (int idx = tid; idx < 2048; idx += 256)
            st4(&us[idx * 4], ld4(&src[idx * 4]));
    }
    {
        const float* src = obs + (size_t)b0 * T * 8;
        for (int idx = tid; idx < 4096; idx += 256)
            st4(&ys[idx * 4], ld4(&src[idx * 4]));
    }
    __syncthreads();

    const int L = tid & 31;
    const int bl = (tid >> 5) * 2 + (L >> 4);
    const int b = b0 + bl;
    const int i = L & 15;

    float arow[16], hrow[16], brow[4];
    #pragma unroll
    for (int k = 0; k < 16; ++k) arow[k] = A[i * 16 + k];
    #pragma unroll
    for (int k = 0; k < 16; ++k) hrow[k] = H[(i & 7) * 16 + k];
    #pragma unroll
    for (int c = 0; c < 4; ++c) brow[c] = Bc[i * 4 + c];

    float s = state0[b * 16 + i];

    #pragma unroll 1
    for (int t = 0; t < T; ++t) {
        float4 uu = ld4(&us[bl * 512 + t * 4]);
        float4 k0 = ld4(&Ks[t * 128 + i * 8]);
        float4 k1 = ld4(&Ks[t * 128 + i * 8 + 4]);
        float yv = ys[bl * 1024 + t * 8 + (i & 7)];

        // s_p = s + DT*(A s + Bc u)
        float a0 = 0.0f, a1 = 0.0f;
        #pragma unroll
        for (int k = 0; k < 8; ++k) {
            a0 = fmaf(arow[k], shfl16(s, k), a0);
            a1 = fmaf(arow[k + 8], shfl16(s, k + 8), a1);
        }
        a0 = fmaf(brow[0], uu.x, a0); a0 = fmaf(brow[1], uu.y, a0);
        a0 = fmaf(brow[2], uu.z, a0); a0 = fmaf(brow[3], uu.w, a0);
        float sp = s + DT * (a0 + a1);
        if (t > 0) g_sp[((size_t)b * T + t) * NS + i] = sp;

        // innov = y - H s_p
        float h0 = 0.0f, h1 = 0.0f;
        #pragma unroll
        for (int k = 0; k < 8; ++k) {
            h0 = fmaf(hrow[k], shfl16(sp, k), h0);
            h1 = fmaf(hrow[k + 8], shfl16(sp, k + 8), h1);
        }
        float iv = yv - (h0 + h1);

        // s = s_p + K innov
        float acc = sp;
        acc = fmaf(k0.x, shfl16(iv, 0), acc);
        acc = fmaf(k0.y, shfl16(iv, 1), acc);
        acc = fmaf(k0.z, shfl16(iv, 2), acc);
        acc = fmaf(k0.w, shfl16(iv, 3), acc);
        acc = fmaf(k1.x, shfl16(iv, 4), acc);
        acc = fmaf(k1.y, shfl16(iv, 5), acc);
        acc = fmaf(k1.z, shfl16(iv, 6), acc);
        acc = fmaf(k1.w, shfl16(iv, 7), acc);
        s = acc;
        out[((size_t)b * T + t) * NS + i] = s;
    }
}

// ============================================================================
// Kernel D: parallel affine prep: c[b][t] = sf[t] - G[t]*sp[t+1].
// One block per (16-batch group, t); G staged in smem (conflict-free pad 17).
// ============================================================================
__global__ __launch_bounds__(256) void kf_cprep(const float* __restrict__ out)
{
    __shared__ float Gs[16 * 17];
    const int t = blockIdx.y;                     // 0..T-2
    const int tid = threadIdx.x;

    if (tid < 256) {
        int i = tid >> 4, j = tid & 15;
        Gs[i * 17 + j] = g_G[t * 256 + tid];
    }
    __syncthreads();

    const int L = tid & 31;
    const int bl = (tid >> 5) * 2 + (L >> 4);
    const int b = blockIdx.x * 16 + bl;
    const int i = L & 15;

    float sf = out[((size_t)b * T + t) * NS + i];
    float sp = g_sp[((size_t)b * T + t + 1) * NS + i];

    float a0 = sf, a1 = 0.f;
    #pragma unroll
    for (int k = 0; k < 8; ++k) {
        a0 = fmaf(-Gs[i * 17 + 2 * k],     shfl16(sp, 2 * k),     a0);
        a1 = fmaf(-Gs[i * 17 + 2 * k + 1], shfl16(sp, 2 * k + 1), a1);
    }
    g_c[((size_t)b * (T - 1) + t) * NS + i] = a0 + a1;
}

// ============================================================================
// Kernel E: backward smoother: ss = G[t] ss + c[b][t].  2 batches/warp.
// ============================================================================
__global__ __launch_bounds__(128) void kf_backward(float* __restrict__ out)
{
    const int L = threadIdx.x & 31;
    const int gw = blockIdx.x * 4 + (threadIdx.x >> 5);
    const int b = gw * 2 + (L >> 4);
    const int i = L & 15;
    const size_t bT = (size_t)b * T;
    const size_t bB = (size_t)b * (T - 1);

    float ss = out[(bT + T - 1) * NS + i];
    float xc[16];
    {
        const float* gp = &g_G[(T - 2) * 256 + i * 16];
        float4 g0 = ld4(gp), g1 = ld4(gp + 4), g2 = ld4(gp + 8), g3 = ld4(gp + 12);
        xc[0] = g0.x; xc[1] = g0.y; xc[2] = g0.z; xc[3] = g0.w;
        xc[4] = g1.x; xc[5] = g1.y; xc[6] = g1.z; xc[7] = g1.w;
        xc[8] = g2.x; xc[9] = g2.y; xc[10] = g2.z; xc[11] = g2.w;
        xc[12] = g3.x; xc[13] = g3.y; xc[14] = g3.z; xc[15] = g3.w;
    }
    float cc = g_c[(bB + T - 2) * NS + i];

    #pragma unroll 2
    for (int t = T - 2; t >= 0; --t) {
        float xn[16], cn = 0.f;
        if (t > 0) {
            const float* gp = &g_G[(t - 1) * 256 + i * 16];
            float4 g0 = ld4(gp), g1 = ld4(gp + 4), g2 = ld4(gp + 8), g3 = ld4(gp + 12);
            xn[0] = g0.x; xn[1] = g0.y; xn[2] = g0.z; xn[3] = g0.w;
            xn[4] = g1.x; xn[5] = g1.y; xn[6] = g1.z; xn[7] = g1.w;
            xn[8] = g2.x; xn[9] = g2.y; xn[10] = g2.z; xn[11] = g2.w;
            xn[12] = g3.x; xn[13] = g3.y; xn[14] = g3.z; xn[15] = g3.w;
            cn = g_c[(bB + t - 1) * NS + i];
        }
        float a0 = cc, a1 = 0.f;
        #pragma unroll
        for (int k = 0; k < 8; ++k) {
            a0 = fmaf(xc[2 * k],     shfl16(ss, 2 * k),     a0);
            a1 = fmaf(xc[2 * k + 1], shfl16(ss, 2 * k + 1), a1);
        }
        ss = a0 + a1;
        out[(bT + t) * NS + i] = ss;
        if (t > 0) {
            #pragma unroll
            for (int k = 0; k < 16; ++k) xc[k] = xn[k];
            cc = cn;
        }
    }
}

extern "C" void kernel_launch(void* const* d_in, const int* in_sizes, int n_in,
                              void* d_out, int out_size) {
    (void)in_sizes; (void)n_in; (void)out_size;
    const float* state0   = (const float*)d_in[0];
    const float* P0       = (const float*)d_in[1];
    const float* controls = (const float*)d_in[2];
    const float* obs      = (const float*)d_in[3];
    const float* A        = (const float*)d_in[4];
    const float* Bc       = (const float*)d_in[5];
    const float* H        = (const float*)d_in[6];
    const float* Q        = (const float*)d_in[7];
    const float* R        = (const float*)d_in[8];
    float* out = (float*)d_out;

    const int smem_states = (T * 128 + SB * T * 4 + SB * T * 8) * 4;   // 163840 B
    cudaFuncSetAttribute(kf_states, cudaFuncAttributeMaxDynamicSharedMemorySize, smem_states);

    kf_gains<<<1, 32>>>(P0, A, H, Q, R);
    kf_smoother_gains<<<T - 1, 32>>>(A, Q);
    kf_states<<<BATCH / SB, 256, smem_states>>>(state0, controls, obs, A, Bc, H, out);
    {
        dim3 grid(BATCH / 16, T - 1);
        kf_cprep<<<grid, 256>>>(out);
    }
    kf_backward<<<BATCH / 8, 128>>>(out);
}

// round 13
// speedup vs baseline: 1.1395x; 1.1395x over previous
#include <cuda_runtime.h>

#define BATCH 2048
#define T 128
#define NS 16
#define MS 8
#define CS 4
#define DT 0.01f
#define SB 16   // batches per block in staged states

// Batch-independent tables (L2-resident).
__device__ float g_K2[T * NS * MS];             // K[t][i][q]
__device__ float g_Pf[(T - 1) * NS * NS];       // P_f[t]
__device__ float g_G[(T - 1) * NS * NS];        // G[t][i][j]
__device__ float g_sp[(size_t)BATCH * T * NS];  // predicted states (t>=1)

__device__ __forceinline__ float4 ld4(const float* p) { return *reinterpret_cast<const float4*>(p); }
__device__ __forceinline__ void st4(float* p, float4 v) { *reinterpret_cast<float4*>(p) = v; }
__device__ __forceinline__ float rcpa(float x) { float y; asm("rcp.approx.f32 %0, %1;" : "=f"(y) : "f"(x)); return y; }
__device__ __forceinline__ float shfl(float v, int s) { return __shfl_sync(0xffffffffu, v, s); }
__device__ __forceinline__ float shflx(float v, int m) { return __shfl_xor_sync(0xffffffffu, v, m); }
__device__ __forceinline__ float shfl16(float v, int s) { return __shfl_sync(0xffffffffu, v, s, 16); }

// ============================================================================
// Kernel A: Riccati recursion with 4 WARPS (issue-bound fix).
// Thread (row = tid>>3, 2-col slice c2 = (tid&7)*2). Phases via padded smem.
// Warp 0 runs the proven shfl-based 8x8 GJ solve.
// ============================================================================
__global__ __launch_bounds__(128) void kf_gains(
    const float* __restrict__ P0, const float* __restrict__ A,
    const float* __restrict__ H, const float* __restrict__ Q,
    const float* __restrict__ R)
{
    __shared__ float Fb[16 * 17], Ftb[16 * 17], Qb[16 * 17];
    __shared__ float Hb[8 * 17], Rb[64];
    __shared__ float P[16 * 17], W[16 * 17], PP[16 * 17];
    __shared__ float PHt[16 * 9], Ss[8 * 9], X2[8 * 17];

    const int tid = threadIdx.x;
    const int lane = tid & 31, wrp = tid >> 5;

    for (int idx = tid; idx < 256; idx += 128) {
        int i = idx >> 4, k = idx & 15;
        float a = A[idx];
        float f = (i == k ? 1.0f : 0.0f) + DT * a;
        Fb[i * 17 + k] = f; Ftb[k * 17 + i] = f;
        Qb[i * 17 + k] = Q[idx];
        P[i * 17 + k] = P0[idx];
    }
    if (tid < 128) {
        int q = tid >> 4, k = tid & 15;
        Hb[q * 17 + k] = H[tid];
    }
    if (tid < 64) Rb[tid] = R[tid];
    __syncthreads();

    const int row = tid >> 3;        // 0..15
    const int c2 = (tid & 7) * 2;    // 0,2,...,14
    const int q8 = tid & 7;          // 0..7

    float frow[16], hq[16];
    #pragma unroll
    for (int k = 0; k < 16; ++k) frow[k] = Fb[row * 17 + k];
    #pragma unroll
    for (int k = 0; k < 16; ++k) hq[k] = Hb[q8 * 17 + k];

    for (int t = 0; t < T; ++t) {
        // ---- P1: W = F * P ----
        float w0 = 0.f, w1 = 0.f;
        #pragma unroll
        for (int k = 0; k < 16; ++k) {
            float fv = frow[k];
            w0 = fmaf(fv, P[k * 17 + c2], w0);
            w1 = fmaf(fv, P[k * 17 + c2 + 1], w1);
        }
        W[row * 17 + c2] = w0; W[row * 17 + c2 + 1] = w1;
        __syncthreads();

        // ---- P2: PP = W * F^T + Q ----
        float a0 = Qb[row * 17 + c2], a1 = Qb[row * 17 + c2 + 1];
        #pragma unroll
        for (int k = 0; k < 16; ++k) {
            float wv = W[row * 17 + k];
            a0 = fmaf(wv, Ftb[k * 17 + c2], a0);
            a1 = fmaf(wv, Ftb[k * 17 + c2 + 1], a1);
        }
        PP[row * 17 + c2] = a0; PP[row * 17 + c2 + 1] = a1;
        __syncthreads();

        // ---- P3: PHt[row][q8] = sum_k PP[row][k] * H[q8][k] ----
        {
            float ph = 0.f;
            #pragma unroll
            for (int k = 0; k < 16; ++k) ph = fmaf(PP[row * 17 + k], hq[k], ph);
            PHt[row * 9 + q8] = ph;
        }
        __syncthreads();

        // ---- P4: S = H*PHt + R  (64 threads, one element each) ----
        if (tid < 64) {
            const int aa = tid >> 3, bb = tid & 7;
            float s = Rb[aa * 8 + bb];
            #pragma unroll
            for (int k = 0; k < 16; ++k)
                s = fmaf(Hb[aa * 17 + k], PHt[k * 9 + bb], s);
            Ss[aa * 9 + bb] = s;
        }
        __syncthreads();

        // ---- P5: warp 0 GJ solve S * X2 = PHt^T (8x8) ----
        if (wrp == 0) {
            const int rr = (lane >> 1) & 7, h = lane & 1, ch = h * 4;
            float s4[4], rhs[8];
            #pragma unroll
            for (int c = 0; c < 4; ++c) s4[c] = Ss[rr * 9 + ch + c];
            #pragma unroll
            for (int j = 0; j < 8; ++j) rhs[j] = PHt[(h * 8 + j) * 9 + rr];

            #pragma unroll
            for (int p = 0; p < 8; ++p) {
                const int hp = (p >= 4) ? 1 : 0;
                float cand = s4[p & 3];
                float f_num = shfl(cand, (rr << 1) | hp);
                float diag  = shfl(cand, (p << 1) | hp);
                const int src = (p << 1) | h;
                float ps0 = shfl(s4[0], src), ps1 = shfl(s4[1], src);
                float ps2 = shfl(s4[2], src), ps3 = shfl(s4[3], src);
                float pr[8];
                #pragma unroll
                for (int j = 0; j < 8; ++j) pr[j] = shfl(rhs[j], src);
                float f = (rr == p) ? 0.0f : f_num * rcpa(diag);
                s4[0] = fmaf(-f, ps0, s4[0]); s4[1] = fmaf(-f, ps1, s4[1]);
                s4[2] = fmaf(-f, ps2, s4[2]); s4[3] = fmaf(-f, ps3, s4[3]);
                #pragma unroll
                for (int j = 0; j < 8; ++j) rhs[j] = fmaf(-f, pr[j], rhs[j]);
            }
            float s01 = (rr & 1) ? s4[1] : s4[0];
            float s23 = (rr & 1) ? s4[3] : s4[2];
            float cand_r = (rr & 2) ? s23 : s01;
            float diag_r = shfl(cand_r, (rr << 1) | ((rr >= 4) ? 1 : 0));
            float invd = rcpa(diag_r);
            if (lane < 16) {
                #pragma unroll
                for (int j = 0; j < 8; ++j) {
                    float xv = rhs[j] * invd;
                    X2[rr * 17 + h * 8 + j] = xv;                 // X2[q=rr][i]
                    g_K2[t * 128 + (h * 8 + j) * 8 + rr] = xv;    // K[i][q]
                }
            }
        }
        __syncthreads();

        // ---- P8: P_f = PP - K*(H*PP);  (H*PP)[q][j] = PHt[j][q] ----
        {
            float kq[8];
            #pragma unroll
            for (int q = 0; q < 8; ++q) kq[q] = X2[q * 17 + row];   // K[row][q]
            float n0 = a0, n1 = a1;
            #pragma unroll
            for (int q = 0; q < 8; ++q) {
                n0 = fmaf(-kq[q], PHt[c2 * 9 + q], n0);
                n1 = fmaf(-kq[q], PHt[(c2 + 1) * 9 + q], n1);
            }
            P[row * 17 + c2] = n0; P[row * 17 + c2 + 1] = n1;
            if (t < T - 1) {
                g_Pf[t * 256 + row * 16 + c2] = n0;
                g_Pf[t * 256 + row * 16 + c2 + 1] = n1;
            }
        }
        __syncthreads();
    }
}

// ============================================================================
// Kernel B: smoother gains, T-1 parallel warps (R11). g_G[t][i][j] row-major.
// ============================================================================
__global__ __launch_bounds__(32) void kf_smoother_gains(
    const float* __restrict__ A, const float* __restrict__ Q)
{
    __shared__ float Fb[16 * 20], Ftb[16 * 20], Qb[16 * 20], Pf[16 * 20];
    const int t = blockIdx.x;
    const int lane = threadIdx.x;

    for (int idx = lane; idx < 256; idx += 32) {
        int i = idx >> 4, k = idx & 15;
        float av = A[idx];
        float f = (i == k ? 1.0f : 0.0f) + DT * av;
        Fb[i * 20 + k] = f; Ftb[k * 20 + i] = f;
        Qb[i * 20 + k] = Q[idx];
        Pf[i * 20 + k] = g_Pf[t * 256 + idx];
    }
    __syncwarp();

    const int row = lane >> 1, h = lane & 1, j0 = h * 8;
    float frow[16];
    #pragma unroll
    for (int k = 0; k < 16; ++k) frow[k] = Fb[row * 20 + k];

    float a[8], w[8];
    #pragma unroll
    for (int j = 0; j < 8; ++j) w[j] = 0.0f;
    #pragma unroll
    for (int k = 0; k < 16; ++k) {
        float fv = frow[k];
        float4 p0 = ld4(&Pf[k * 20 + j0]);
        float4 p1 = ld4(&Pf[k * 20 + j0 + 4]);
        w[0] = fmaf(fv, p0.x, w[0]); w[1] = fmaf(fv, p0.y, w[1]);
        w[2] = fmaf(fv, p0.z, w[2]); w[3] = fmaf(fv, p0.w, w[3]);
        w[4] = fmaf(fv, p1.x, w[4]); w[5] = fmaf(fv, p1.y, w[5]);
        w[6] = fmaf(fv, p1.z, w[6]); w[7] = fmaf(fv, p1.w, w[7]);
    }
    {
        float wk[16];
        #pragma unroll
        for (int j = 0; j < 8; ++j) {
            wk[j0 + j] = w[j];
            wk[(j0 ^ 8) + j] = shflx(w[j], 1);
        }
        float4 q0 = ld4(&Qb[row * 20 + j0]);
        float4 q1 = ld4(&Qb[row * 20 + j0 + 4]);
        a[0] = q0.x; a[1] = q0.y; a[2] = q0.z; a[3] = q0.w;
        a[4] = q1.x; a[5] = q1.y; a[6] = q1.z; a[7] = q1.w;
        #pragma unroll
        for (int k = 0; k < 16; ++k) {
            float wv = wk[k];
            float4 f0 = ld4(&Ftb[k * 20 + j0]);
            float4 f1 = ld4(&Ftb[k * 20 + j0 + 4]);
            a[0] = fmaf(wv, f0.x, a[0]); a[1] = fmaf(wv, f0.y, a[1]);
            a[2] = fmaf(wv, f0.z, a[2]); a[3] = fmaf(wv, f0.w, a[3]);
            a[4] = fmaf(wv, f1.x, a[4]); a[5] = fmaf(wv, f1.y, a[5]);
            a[6] = fmaf(wv, f1.z, a[6]); a[7] = fmaf(wv, f1.w, a[7]);
        }
    }
    #pragma unroll
    for (int p = 0; p < 16; ++p) {
        const int hp = (p >= 8) ? 1 : 0;
        float cand = a[p & 7];
        float f_num = shfl(cand, (row << 1) | hp);
        float diag  = shfl(cand, (p << 1) | hp);
        const int src = (p << 1) | h;
        float pa[8], pw[8];
        #pragma unroll
        for (int j = 0; j < 8; ++j) { pa[j] = shfl(a[j], src); pw[j] = shfl(w[j], src); }
        float f = (row == p) ? 0.0f : f_num * rcpa(diag);
        #pragma unroll
        for (int j = 0; j < 8; ++j) {
            a[j] = fmaf(-f, pa[j], a[j]);
            w[j] = fmaf(-f, pw[j], w[j]);
        }
    }
    const int ri = row & 7;
    float s01 = (ri & 1) ? a[1] : a[0];
    float s23 = (ri & 1) ? a[3] : a[2];
    float s45 = (ri & 1) ? a[5] : a[4];
    float s67 = (ri & 1) ? a[7] : a[6];
    float t0 = (ri & 2) ? s23 : s01;
    float t1 = (ri & 2) ? s67 : s45;
    float cand_r = (ri & 4) ? t1 : t0;
    float diag_r = shfl(cand_r, (row << 1) | ((row >= 8) ? 1 : 0));
    float invd = rcpa(diag_r);
    #pragma unroll
    for (int j = 0; j < 8; ++j)
        g_G[t * 256 + (j0 + j) * 16 + row] = w[j] * invd;
}

// ============================================================================
// Kernel C: forward state filter, smem-staged (measured best).
// ============================================================================
__global__ __launch_bounds__(256) void kf_states(
    const float* __restrict__ state0, const float* __restrict__ controls,
    const float* __restrict__ obs, const float* __restrict__ A,
    const float* __restrict__ Bc, const float* __restrict__ H,
    float* __restrict__ out)
{
    extern __shared__ float sm[];
    float* Ks = sm;                        // T*128 floats
    float* us = Ks + T * 128;              // SB*T*4
    float* ys = us + SB * T * 4;           // SB*T*8

    const int tid = threadIdx.x;
    const int b0 = blockIdx.x * SB;

    for (int idx = tid; idx < 4096; idx += 256)
        st4(&Ks[idx * 4], ld4(&g_K2[idx * 4]));
    {
        const float* src = controls + (size_t)b0 * T * 4;
        for (int idx = tid; idx < 2048; idx += 256)
            st4(&us[idx * 4], ld4(&src[idx * 4]));
    }
    {
        const float* src = obs + (size_t)b0 * T * 8;
        for (int idx = tid; idx < 4096; idx += 256)
            st4(&ys[idx * 4], ld4(&src[idx * 4]));
    }
    __syncthreads();

    const int L = tid & 31;
    const int bl = (tid >> 5) * 2 + (L >> 4);
    const int b = b0 + bl;
    const int i = L & 15;

    float arow[16], hrow[16], brow[4];
    #pragma unroll
    for (int k = 0; k < 16; ++k) arow[k] = A[i * 16 + k];
    #pragma unroll
    for (int k = 0; k < 16; ++k) hrow[k] = H[(i & 7) * 16 + k];
    #pragma unroll
    for (int c = 0; c < 4; ++c) brow[c] = Bc[i * 4 + c];

    float s = state0[b * 16 + i];

    #pragma unroll 1
    for (int t = 0; t < T; ++t) {
        float4 uu = ld4(&us[bl * 512 + t * 4]);
        float4 k0 = ld4(&Ks[t * 128 + i * 8]);
        float4 k1 = ld4(&Ks[t * 128 + i * 8 + 4]);
        float yv = ys[bl * 1024 + t * 8 + (i & 7)];

        float a0 = 0.0f, a1 = 0.0f;
        #pragma unroll
        for (int k = 0; k < 8; ++k) {
            a0 = fmaf(arow[k], shfl16(s, k), a0);
            a1 = fmaf(arow[k + 8], shfl16(s, k + 8), a1);
        }
        a0 = fmaf(brow[0], uu.x, a0); a0 = fmaf(brow[1], uu.y, a0);
        a0 = fmaf(brow[2], uu.z, a0); a0 = fmaf(brow[3], uu.w, a0);
        float sp = s + DT * (a0 + a1);
        if (t > 0) g_sp[((size_t)b * T + t) * NS + i] = sp;

        float h0 = 0.0f, h1 = 0.0f;
        #pragma unroll
        for (int k = 0; k < 8; ++k) {
            h0 = fmaf(hrow[k], shfl16(sp, k), h0);
            h1 = fmaf(hrow[k + 8], shfl16(sp, k + 8), h1);
        }
        float iv = yv - (h0 + h1);

        float acc = sp;
        acc = fmaf(k0.x, shfl16(iv, 0), acc);
        acc = fmaf(k0.y, shfl16(iv, 1), acc);
        acc = fmaf(k0.z, shfl16(iv, 2), acc);
        acc = fmaf(k0.w, shfl16(iv, 3), acc);
        acc = fmaf(k1.x, shfl16(iv, 4), acc);
        acc = fmaf(k1.y, shfl16(iv, 5), acc);
        acc = fmaf(k1.z, shfl16(iv, 6), acc);
        acc = fmaf(k1.w, shfl16(iv, 7), acc);
        s = acc;
        out[((size_t)b * T + t) * NS + i] = s;
    }
}

// ============================================================================
// Kernel D: backward smoother (R11 measured: 90.8us).
// ============================================================================
__global__ __launch_bounds__(128) void kf_backward(float* __restrict__ out)
{
    const int L = threadIdx.x & 31;
    const int gw = blockIdx.x * 4 + (threadIdx.x >> 5);
    const int b = gw * 2 + (L >> 4);
    const int i = L & 15;

    float ss = out[((size_t)b * T + (T - 1)) * NS + i];
    float xc[16];
    {
        const float* gp = &g_G[(T - 2) * 256 + i * 16];
        float4 g0 = ld4(gp), g1 = ld4(gp + 4), g2 = ld4(gp + 8), g3 = ld4(gp + 12);
        xc[0] = g0.x; xc[1] = g0.y; xc[2] = g0.z; xc[3] = g0.w;
        xc[4] = g1.x; xc[5] = g1.y; xc[6] = g1.z; xc[7] = g1.w;
        xc[8] = g2.x; xc[9] = g2.y; xc[10] = g2.z; xc[11] = g2.w;
        xc[12] = g3.x; xc[13] = g3.y; xc[14] = g3.z; xc[15] = g3.w;
    }
    float spn_c = g_sp[((size_t)b * T + (T - 1)) * NS + i];
    float sf_c  = out[((size_t)b * T + (T - 2)) * NS + i];

    #pragma unroll 1
    for (int t = T - 2; t >= 0; --t) {
        float xn[16]; float spn_n = 0.0f, sf_n = 0.0f;
        if (t > 0) {
            const float* gp = &g_G[(t - 1) * 256 + i * 16];
            float4 g0 = ld4(gp), g1 = ld4(gp + 4), g2 = ld4(gp + 8), g3 = ld4(gp + 12);
            xn[0] = g0.x; xn[1] = g0.y; xn[2] = g0.z; xn[3] = g0.w;
            xn[4] = g1.x; xn[5] = g1.y; xn[6] = g1.z; xn[7] = g1.w;
            xn[8] = g2.x; xn[9] = g2.y; xn[10] = g2.z; xn[11] = g2.w;
            xn[12] = g3.x; xn[13] = g3.y; xn[14] = g3.z; xn[15] = g3.w;
            spn_n = g_sp[((size_t)b * T + t) * NS + i];
            sf_n  = out[((size_t)b * T + t - 1) * NS + i];
        }
        float d = ss - spn_c;
        float m0 = 0.0f, m1 = 0.0f;
        #pragma unroll
        for (int j = 0; j < 8; ++j) {
            m0 = fmaf(shfl16(d, j), xc[j], m0);
            m1 = fmaf(shfl16(d, j + 8), xc[j + 8], m1);
        }
        ss = sf_c + m0 + m1;
        out[((size_t)b * T + t) * NS + i] = ss;
        if (t > 0) {
            #pragma unroll
            for (int j = 0; j < 16; ++j) xc[j] = xn[j];
            spn_c = spn_n; sf_c = sf_n;
        }
    }
}

extern "C" void kernel_launch(void* const* d_in, const int* in_sizes, int n_in,
                              void* d_out, int out_size) {
    (void)in_sizes; (void)n_in; (void)out_size;
    const float* state0   = (const float*)d_in[0];
    const float* P0       = (const float*)d_in[1];
    const float* controls = (const float*)d_in[2];
    const float* obs      = (const float*)d_in[3];
    const float* A        = (const float*)d_in[4];
    const float* Bc       = (const float*)d_in[5];
    const float* H        = (const float*)d_in[6];
    const float* Q        = (const float*)d_in[7];
    const float* R        = (const float*)d_in[8];
    float* out = (float*)d_out;

    const int smem_states = (T * 128 + SB * T * 4 + SB * T * 8) * 4;   // 163840 B
    cudaFuncSetAttribute(kf_states, cudaFuncAttributeMaxDynamicSharedMemorySize, smem_states);

    kf_gains<<<1, 128>>>(P0, A, H, Q, R);
    kf_smoother_gains<<<T - 1, 32>>>(A, Q);
    kf_states<<<BATCH / SB, 256, smem_states>>>(state0, controls, obs, A, Bc, H, out);
    kf_backward<<<BATCH / 8, 128>>>(out);
}